// round 16
// baseline (speedup 1.0000x reference)
#include <cuda_runtime.h>
#include <cuda_bf16.h>
#include <math.h>
#include <stdint.h>

// Problem constants
#define BB 4
#define NN 1024
#define CC 128
#define HH 256
#define WW 256
#define MM 1024
#define GRIDC 8

// Main tiling: 64 query rows x 128 candidate cols per block
#define TQ 64
#define TC 128
#define QT (NN / TQ)                     // 16
#define CTILES (MM / TC)                 // 8
#define HALF_BLOCKS (BB * QT * CTILES)   // 512
#define MAIN_BLOCKS (2 * HALF_BLOCKS)    // 1024
#define NTOP (CTILES * 8)                // 64 partials per row

// smem (bytes): A tile 64x(128+8) bf16 | B tile 128x(128+8) | qc(512B) | cc(1KB)
#define ROWB 272
#define SM_A   0
#define SM_B   17408
#define SM_QC  52224
#define SM_CC  52736
#define SMEM_TOTAL 53760
#define DSTRIDE 130
// dots overlay [0, 64*130*4 = 33280) — inside A+B region, below SM_QC. safe.

// Scratch (device globals)
__device__ float g_a [BB * NN * CC];
__device__ float g_wa[BB * NN * CC];
__device__ float g_gd[BB * MM * CC];
__device__ __nv_bfloat16 g_a_bf [BB * NN * 256];   // [row][0:128]=hi,[128:256]=lo
__device__ __nv_bfloat16 g_wa_bf[BB * NN * 256];
__device__ __nv_bfloat16 g_gd_bf[BB * MM * 256];
__device__ float g_fos_topv[BB * NN * NTOP];       // approx dots
__device__ int   g_fos_topi[BB * NN * NTOP];
__device__ float g_sos_topv[BB * NN * NTOP];
__device__ int   g_sos_topi[BB * NN * NTOP];
__device__ float g_fos_row[BB * NN];
__device__ float g_vis_row[BB * NN];
__device__ float g_sos_row[BB * NN];

__device__ __forceinline__ uint32_t smem_u32(const void* p) {
    uint32_t a;
    asm("{ .reg .u64 t; cvta.to.shared.u64 t, %1; cvt.u32.u64 %0, t; }"
        : "=r"(a) : "l"(p));
    return a;
}

#define LDMATRIX_X4(r0, r1, r2, r3, addr) \
    asm volatile("ldmatrix.sync.aligned.m8n8.x4.shared.b16 {%0,%1,%2,%3}, [%4];" \
                 : "=r"(r0), "=r"(r1), "=r"(r2), "=r"(r3) : "r"(addr))
#define MMA_BF16(d, a, b) \
    asm volatile("mma.sync.aligned.m16n8k16.row.col.f32.bf16.bf16.f32 " \
                 "{%0,%1,%2,%3}, {%4,%5,%6,%7}, {%8,%9}, {%0,%1,%2,%3};" \
                 : "+f"((d)[0]), "+f"((d)[1]), "+f"((d)[2]), "+f"((d)[3]) \
                 : "r"((a)[0]), "r"((a)[1]), "r"((a)[2]), "r"((a)[3]), \
                   "r"((b)[0]), "r"((b)[1]))

// ---------------------------------------------------------------------------
// Prep kernels
// ---------------------------------------------------------------------------
__device__ __forceinline__ float block_norm(float v) {
    __shared__ float red[4];
    float s = v * v;
    #pragma unroll
    for (int o = 16; o > 0; o >>= 1) s += __shfl_down_sync(0xffffffffu, s, o);
    if ((threadIdx.x & 31) == 0) red[threadIdx.x >> 5] = s;
    __syncthreads();
    return v / (sqrtf(red[0] + red[1] + red[2] + red[3]) + 1e-8f);
}
__device__ __forceinline__ void write_split(__nv_bfloat16* dst, int c, float v) {
    __nv_bfloat16 h = __float2bfloat16(v);
    dst[c] = h;
    dst[128 + c] = __float2bfloat16(v - __bfloat162float(h));
}

__global__ void prep_a_kernel(const float* __restrict__ kp1_desc) {
    int c = threadIdx.x;
    float v = block_norm(kp1_desc[(size_t)blockIdx.x * CC + c]);
    g_a[(size_t)blockIdx.x * CC + c] = v;
    write_split(g_a_bf + (size_t)blockIdx.x * 256, c, v);
}

template<bool GD>
__global__ void prep_bil_kernel(const float* __restrict__ w_kp1,
                                const float* __restrict__ desc2) {
    int idx = blockIdx.x;
    int c = threadIdx.x;
    int b;
    float px, py;
    if (GD) {
        b = idx / MM; int m = idx - b * MM;
        px = ((float)(m & 31) + 0.5f) * (float)GRIDC;
        py = ((float)(m >> 5) + 0.5f) * (float)GRIDC;
    } else {
        b = idx / NN; int n = idx - b * NN;
        px = w_kp1[(size_t)(b * NN + n) * 2 + 0];
        py = w_kp1[(size_t)(b * NN + n) * 2 + 1];
    }
    float x = fminf(fmaxf(px, 0.0f), (float)(WW - 1));
    float y = fminf(fmaxf(py, 0.0f), (float)(HH - 1));
    float x0f = floorf(x), y0f = floorf(y);
    float wx = x - x0f, wy = y - y0f;
    int x0 = (int)x0f, y0 = (int)y0f;
    int x1 = min(x0 + 1, WW - 1), y1 = min(y0 + 1, HH - 1);
    const float* base = desc2 + (size_t)(b * CC + c) * (HH * WW);
    float v00 = base[y0 * WW + x0];
    float v01 = base[y0 * WW + x1];
    float v10 = base[y1 * WW + x0];
    float v11 = base[y1 * WW + x1];
    float v = v00 * (1.0f - wy) * (1.0f - wx) + v01 * (1.0f - wy) * wx
            + v10 * wy * (1.0f - wx)          + v11 * wy * wx;
    v = block_norm(v);
    if (GD) {
        g_gd[(size_t)idx * CC + c] = v;
        write_split(g_gd_bf + (size_t)idx * 256, c, v);
    } else {
        g_wa[(size_t)idx * CC + c] = v;
        write_split(g_wa_bf + (size_t)idx * 256, c, v);
    }
}

// ---------------------------------------------------------------------------
__device__ __forceinline__ float compute_vis(const float* __restrict__ kp1,
                                             const float* __restrict__ homo,
                                             int b, int n) {
    float kx = kp1[(size_t)(b * NN + n) * 2 + 0];
    float ky = kp1[(size_t)(b * NN + n) * 2 + 1];
    const float* hm = homo + b * 9;
    float den = hm[6] * kx + hm[7] * ky + hm[8] + 1e-8f;
    float wkx = (hm[0] * kx + hm[1] * ky + hm[2]) / den;
    float wky = (hm[3] * kx + hm[4] * ky + hm[5]) / den;
    return (wkx >= 0.0f && wkx <= (float)(WW - 1) &&
            wky >= 0.0f && wky <= (float)(HH - 1)) ? 1.0f : 0.0f;
}

// ---------------------------------------------------------------------------
// Main kernel (HMMA). Blocks [0,512): FOS; [512,1024): SOS.
// 64x128 tile; approx dot = hi*hi + lo*hi + hi*lo (3 bf16 GEMM passes).
// Warp grid 2x4, warp tile 32x32. B via NON-trans ldmatrix (stored [n][k]).
// ---------------------------------------------------------------------------
__global__ __launch_bounds__(256, 2) void main_kernel(const float* __restrict__ w_kp1) {
    extern __shared__ char smc[];
    uint32_t sb = smem_u32(smc);
    float* qc = (float*)(smc + SM_QC);
    float* cc = (float*)(smc + SM_CC);

    int tid = threadIdx.x;
    int wid = tid >> 5, lane = tid & 31;
    int wr = wid >> 2, wc = wid & 3;       // 2x4 warp grid
    int bid = blockIdx.x;
    bool is_sos = bid >= HALF_BLOCKS;
    int lbid = is_sos ? bid - HALF_BLOCKS : bid;
    int ct = lbid & (CTILES - 1);
    int qt = (lbid >> 3) & (QT - 1);
    int b  = lbid >> 7;
    int n0 = qt * TQ;
    int m_base = ct * TC;

    const __nv_bfloat16* asrc = (is_sos ? g_wa_bf : g_a_bf) + (size_t)(b * NN + n0) * 256;
    const __nv_bfloat16* bsrc = (is_sos ? g_wa_bf : g_gd_bf)
                              + (size_t)(b * (is_sos ? NN : MM) + m_base) * 256;

    // coords: qc = 64 query coords (128 floats), cc = 128 candidate coords
    if (tid < 128) qc[tid] = w_kp1[(size_t)(b * NN + n0 + (tid >> 1)) * 2 + (tid & 1)];
    {
        int r = tid >> 1, comp = tid & 1;
        if (is_sos) {
            cc[tid] = w_kp1[(size_t)(b * NN + m_base + r) * 2 + comp];
        } else {
            int m = m_base + r;
            cc[tid] = comp ? (float)((m >> 5) * GRIDC + 4)
                           : (float)((m & 31) * GRIDC + 4);
        }
    }

    float acc[2][4][4];
    #pragma unroll
    for (int mt = 0; mt < 2; mt++)
        #pragma unroll
        for (int nt = 0; nt < 4; nt++)
            #pragma unroll
            for (int e = 0; e < 4; e++) acc[mt][nt][e] = 0.0f;

    #pragma unroll 1
    for (int p = 0; p < 3; p++) {
        int aoff = (p == 1) ? 128 : 0;
        int boff = (p == 2) ? 128 : 0;
        __syncthreads();
        #pragma unroll
        for (int j = 0; j < 4; j++) {        // A: 64 rows x 16 chunks = 1024
            int idx = tid + j * 256;
            int r = idx >> 4, c8 = idx & 15;
            *(float4*)(smc + SM_A + r * ROWB + c8 * 16) =
                *(const float4*)(asrc + (size_t)r * 256 + aoff + c8 * 8);
        }
        #pragma unroll
        for (int j = 0; j < 8; j++) {        // B: 128 rows x 16 chunks = 2048
            int idx = tid + j * 256;
            int r = idx >> 4, c8 = idx & 15;
            *(float4*)(smc + SM_B + r * ROWB + c8 * 16) =
                *(const float4*)(bsrc + (size_t)r * 256 + boff + c8 * 8);
        }
        __syncthreads();

        #pragma unroll
        for (int s = 0; s < 8; s++) {
            int k0 = s * 16;
            uint32_t af[2][4], bf2[4][2];
            #pragma unroll
            for (int mt = 0; mt < 2; mt++) {
                uint32_t addr = sb + SM_A
                    + (uint32_t)(wr * 32 + mt * 16 + (lane & 15)) * ROWB
                    + (uint32_t)(k0 + (lane >> 4) * 8) * 2;
                LDMATRIX_X4(af[mt][0], af[mt][1], af[mt][2], af[mt][3], addr);
            }
            #pragma unroll
            for (int ntp = 0; ntp < 2; ntp++) {
                int g = lane >> 3;
                uint32_t addr = sb + SM_B
                    + (uint32_t)(wc * 32 + ntp * 16 + (g >> 1) * 8 + (lane & 7)) * ROWB
                    + (uint32_t)(k0 + (g & 1) * 8) * 2;
                uint32_t t0, t1, t2, t3;
                LDMATRIX_X4(t0, t1, t2, t3, addr);   // NON-trans: B stored [n][k]
                bf2[2 * ntp][0] = t0;     bf2[2 * ntp][1] = t1;
                bf2[2 * ntp + 1][0] = t2; bf2[2 * ntp + 1][1] = t3;
            }
            #pragma unroll
            for (int mt = 0; mt < 2; mt++)
                #pragma unroll
                for (int nt = 0; nt < 4; nt++)
                    MMA_BF16(acc[mt][nt], af[mt], bf2[nt]);
        }
    }
    __syncthreads();

    // ---- mask + stage masked dots into dots[64][DSTRIDE] ----
    float* dots = (float*)smc;
    #pragma unroll
    for (int mt = 0; mt < 2; mt++) {
        #pragma unroll
        for (int rr = 0; rr < 2; rr++) {
            int row = wr * 32 + mt * 16 + (lane >> 2) + rr * 8;
            int n_glob = n0 + row;
            float qx = qc[2 * row], qy = qc[2 * row + 1];
            #pragma unroll
            for (int nt = 0; nt < 4; nt++) {
                int col = wc * 32 + nt * 8 + 2 * (lane & 3);
                float d0 = acc[mt][nt][2 * rr + 0];
                float d1 = acc[mt][nt][2 * rr + 1];
                #pragma unroll
                for (int e = 0; e < 2; e++) {
                    float d = e ? d1 : d0;
                    int cl = col + e;
                    int m = m_base + cl;
                    float dx = qx - cc[2 * cl], dy = qy - cc[2 * cl + 1];
                    bool masked = (dx * dx + dy * dy < 256.0f) ||
                                  (is_sos && m == n_glob);
                    if (e) d1 = masked ? -1e30f : d;
                    else   d0 = masked ? -1e30f : d;
                }
                *(float2*)(dots + (size_t)row * DSTRIDE + col) = make_float2(d0, d1);
            }
        }
    }
    __syncthreads();

    // ---- per-row top-8 scan (threads 0..63), store vals + indices ----
    if (tid < TQ) {
        float mv[8]; int mi[8];
        #pragma unroll
        for (int j = 0; j < 8; j++) { mv[j] = -1e30f; mi[j] = 0; }
        float w8 = -1e30f;
        const float* drow = dots + (size_t)tid * DSTRIDE;
        #pragma unroll 4
        for (int i = 0; i < TC; i++) {
            float val = drow[i];
            if (val > w8) {
                bool done = false;
                #pragma unroll
                for (int j = 0; j < 8; j++)
                    if (!done && mv[j] == w8) { mv[j] = val; mi[j] = m_base + i; done = true; }
                w8 = mv[0];
                #pragma unroll
                for (int j = 1; j < 8; j++) w8 = fminf(w8, mv[j]);
            }
        }
        size_t base = (size_t)(b * NN + n0 + tid) * NTOP + ct * 8;
        if (is_sos) {
            #pragma unroll
            for (int j = 0; j < 8; j++) {
                g_sos_topv[base + j] = mv[j];
                g_sos_topi[base + j] = mi[j];
            }
        } else {
            #pragma unroll
            for (int j = 0; j < 8; j++) {
                g_fos_topv[base + j] = mv[j];
                g_fos_topi[base + j] = mi[j];
            }
        }
    }
}

// ---------------------------------------------------------------------------
__device__ __forceinline__ void bitonic32(float& v, int& i) {
    unsigned lane = threadIdx.x & 31;
    #pragma unroll
    for (int k = 2; k <= 32; k <<= 1) {
        #pragma unroll
        for (int j = k >> 1; j > 0; j >>= 1) {
            float pv = __shfl_xor_sync(0xffffffffu, v, j);
            int   pi = __shfl_xor_sync(0xffffffffu, i, j);
            bool up = ((lane & k) == 0) || (k == 32);
            bool keepmin = (up == ((lane & j) == 0));
            bool take = keepmin ? (pv < v) : (pv > v);
            if (take) { v = pv; i = pi; }
        }
    }
}
// merge 64 partials -> top-16 ascending keys in lanes 0-15
__device__ __forceinline__ void merge_top16(float& key, int& idx, float kB, int iB) {
    unsigned lane = threadIdx.x & 31;
    bitonic32(key, idx);
    bitonic32(kB, iB);
    float kBs = __shfl_sync(0xffffffffu, kB, (lane - 16) & 31);
    int   iBs = __shfl_sync(0xffffffffu, iB, (lane - 16) & 31);
    float cand = (lane < 16) ? key : kBs;
    int   candi = (lane < 16) ? idx : iBs;
    bitonic32(cand, candi);
    key = cand; idx = candi;
}
// exact fp32 rescore of the 16 candidates (2 lanes/candidate), re-rank.
__device__ __forceinline__ void rescore16(float key, int idx,
                                          const float* __restrict__ rowp,
                                          const float* __restrict__ candbase,
                                          float& okey, int& oidx) {
    unsigned lane = threadIdx.x & 31;
    float k_s = __shfl_sync(0xffffffffu, key, lane >> 1);
    int   i_s = __shfl_sync(0xffffffffu, idx, lane >> 1);
    float dp = 0.0f;
    if (k_s < 1e29f) {
        const float4* pr = (const float4*)rowp;
        const float4* pc = (const float4*)(candbase + (size_t)i_s * CC);
        int h = lane & 1;
        #pragma unroll
        for (int kk = 0; kk < 16; kk++) {
            float4 x = pr[h * 16 + kk], y = pc[h * 16 + kk];
            dp += x.x * y.x + x.y * y.y + x.z * y.z + x.w * y.w;
        }
    }
    dp += __shfl_xor_sync(0xffffffffu, dp, 1);
    float ex = __shfl_sync(0xffffffffu, dp, (2 * lane) & 31);
    okey = (lane < 16 && key < 1e29f) ? -ex : 1e30f;
    oidx = idx;
    bitonic32(okey, oidx);
}

// ---------------------------------------------------------------------------
// Epilogue: warp per row; top-16 approx merge -> exact fp32 rescore -> top-8;
// pos, vis, d1 gather.
// ---------------------------------------------------------------------------
__global__ __launch_bounds__(256) void epilogue_kernel(const float* __restrict__ kp1,
                                                       const float* __restrict__ homo) {
    int w = threadIdx.x >> 5, lane = threadIdx.x & 31;
    int row = blockIdx.x * 8 + w;
    int b = row >> 10, n = row & 1023;

    const float* arow  = g_a  + (size_t)row * CC;
    const float* warow = g_wa + (size_t)row * CC;

    float4 av = *(const float4*)(arow  + 4 * lane);
    float4 wv = *(const float4*)(warow + 4 * lane);
    float d0 = av.x - wv.x, d1 = av.y - wv.y, d2 = av.z - wv.z, d3 = av.w - wv.w;
    float s = d0 * d0 + d1 * d1 + d2 * d2 + d3 * d3;
    #pragma unroll
    for (int o = 16; o > 0; o >>= 1) s += __shfl_xor_sync(0xffffffffu, s, o);
    float pos = sqrtf(s);

    // ---- FOS: merge approx top-16, exact rescore vs gd ----
    float fA = -g_fos_topv[(size_t)row * NTOP + lane];
    float fB = -g_fos_topv[(size_t)row * NTOP + 32 + lane];
    int   jA =  g_fos_topi[(size_t)row * NTOP + lane];
    int   jB =  g_fos_topi[(size_t)row * NTOP + 32 + lane];
    merge_top16(fA, jA, fB, jB);
    float fkey; int fidx;
    rescore16(fA, jA, arow, g_gd + (size_t)b * MM * CC, fkey, fidx);
    float fdist = (fkey > 1e29f) ? 10.0f
                                 : sqrtf(fmaxf(2.0f + 2.0f * fkey, 0.0f) + 1e-8f);
    float f = (lane < 8) ? fmaxf(pos - fdist + 1.0f, 0.0f) : 0.0f;
    #pragma unroll
    for (int o = 16; o > 0; o >>= 1) f += __shfl_xor_sync(0xffffffffu, f, o);

    // ---- SOS: merge approx top-16, exact rescore vs wa ----
    float sA = -g_sos_topv[(size_t)row * NTOP + lane];
    float sB = -g_sos_topv[(size_t)row * NTOP + 32 + lane];
    int   iA =  g_sos_topi[(size_t)row * NTOP + lane];
    int   iB =  g_sos_topi[(size_t)row * NTOP + 32 + lane];
    merge_top16(sA, iA, sB, iB);
    float skey; int sidx;
    rescore16(sA, iA, warow, g_wa + (size_t)b * NN * CC, skey, sidx);

    // d1 at the 8 selected indices: quad (4 lanes) per index
    int j = lane >> 2, q = lane & 3;
    float d2neg = __shfl_sync(0xffffffffu, skey, j);
    int   cidx  = __shfl_sync(0xffffffffu, sidx, j);
    const float4* pa = (const float4*)arow;
    const float4* pb = (const float4*)(g_a + (size_t)(b * NN + cidx) * CC);
    float dp = 0.0f;
    #pragma unroll
    for (int kk = 0; kk < 8; kk++) {
        float4 x = pa[q * 8 + kk], y = pb[q * 8 + kk];
        dp += x.x * y.x + x.y * y.y + x.z * y.z + x.w * y.w;
    }
    dp += __shfl_xor_sync(0xffffffffu, dp, 1);
    dp += __shfl_xor_sync(0xffffffffu, dp, 2);
    float d1v = sqrtf(fmaxf(2.0f - 2.0f * dp, 0.0f) + 1e-8f);
    float d2v = sqrtf(fmaxf(2.0f + 2.0f * d2neg, 0.0f) + 1e-8f);
    float t = (d2neg < 1e29f) ? (d1v - d2v) : 0.0f;
    float t2 = (q == 0) ? t * t : 0.0f;
    #pragma unroll
    for (int o = 16; o > 0; o >>= 1) t2 += __shfl_xor_sync(0xffffffffu, t2, o);

    if (lane == 0) {
        float vis = compute_vis(kp1, homo, b, n);
        g_fos_row[row] = f * vis;
        g_vis_row[row] = vis;
        g_sos_row[row] = sqrtf(t2 + 1e-8f) * vis;
    }
}

// ---------------------------------------------------------------------------
__global__ void finalize_kernel(float* __restrict__ out) {
    __shared__ float sf[1024], sv[1024], ss[1024];
    int t = threadIdx.x;
    float f = 0.0f, v = 0.0f, s = 0.0f;
    #pragma unroll
    for (int i = 0; i < 4; i++) {
        f += g_fos_row[t + 1024 * i];
        v += g_vis_row[t + 1024 * i];
        s += g_sos_row[t + 1024 * i];
    }
    sf[t] = f; sv[t] = v; ss[t] = s;
    __syncthreads();
    for (int o = 512; o > 0; o >>= 1) {
        if (t < o) {
            sf[t] += sf[t + o];
            sv[t] += sv[t + o];
            ss[t] += ss[t + o];
        }
        __syncthreads();
    }
    if (t == 0) {
        float cnt = fmaxf(sv[0], 1.0f);
        out[0] = sf[0] / (cnt * 8.0f) + ss[0] / cnt;
    }
}

// ---------------------------------------------------------------------------
extern "C" void kernel_launch(void* const* d_in, const int* in_sizes, int n_in,
                              void* d_out, int out_size) {
    const float* kp1      = (const float*)d_in[0];
    const float* w_kp1    = (const float*)d_in[1];
    const float* kp1_desc = (const float*)d_in[2];
    const float* desc2    = (const float*)d_in[3];
    const float* homo12   = (const float*)d_in[4];
    (void)in_sizes; (void)n_in; (void)out_size;

    cudaFuncSetAttribute(main_kernel,
                         cudaFuncAttributeMaxDynamicSharedMemorySize, SMEM_TOTAL);

    prep_a_kernel<<<BB * NN, CC>>>(kp1_desc);
    prep_bil_kernel<false><<<BB * NN, CC>>>(w_kp1, desc2);
    prep_bil_kernel<true ><<<BB * MM, CC>>>(w_kp1, desc2);
    main_kernel<<<MAIN_BLOCKS, 256, SMEM_TOTAL>>>(w_kp1);
    epilogue_kernel<<<BB * NN / 8, 256>>>(kp1, homo12);
    finalize_kernel<<<1, 1024>>>((float*)d_out);
}

// round 17
// speedup vs baseline: 1.3149x; 1.3149x over previous
#include <cuda_runtime.h>
#include <cuda_bf16.h>
#include <math.h>
#include <stdint.h>

// Problem constants
#define BB 4
#define NN 1024
#define CC 128
#define HH 256
#define WW 256
#define MM 1024
#define GRIDC 8

// Main tiling: 64 query rows x 128 candidate cols per block
#define TQ 64
#define TC 128
#define QT (NN / TQ)                     // 16
#define CTILES (MM / TC)                 // 8
#define HALF_BLOCKS (BB * QT * CTILES)   // 512
#define MAIN_BLOCKS (2 * HALF_BLOCKS)    // 1024
#define NTOP (CTILES * 8)                // 64 partials per row

// smem (bytes):
//   A: 64 rows x 264 bf16 (hi|lo + pad)  = 33792
//   B: 128 rows x 136 bf16 (hi + pad)    = 34816
//   qc 512 | cc 1024
#define ROWA 528
#define ROWB 272
#define SM_A   0
#define SM_B   33792
#define SM_QC  68608
#define SM_CC  69120
#define SMEM_TOTAL 70144
#define DSTRIDE 130
// dots overlay [0, 64*130*4=33280) in A region; sel staging in B region.

// Scratch (device globals)
__device__ float g_a [BB * NN * CC];
__device__ float g_wa[BB * NN * CC];
__device__ float g_gd[BB * MM * CC];
__device__ __nv_bfloat16 g_a_bf [BB * NN * 256];   // [row][0:128]=hi,[128:256]=lo
__device__ __nv_bfloat16 g_wa_bf[BB * NN * 256];
__device__ __nv_bfloat16 g_gd_bf[BB * MM * 256];
__device__ float g_fos_topv[BB * NN * NTOP];       // approx dots
__device__ int   g_fos_topi[BB * NN * NTOP];
__device__ float g_sos_topv[BB * NN * NTOP];
__device__ int   g_sos_topi[BB * NN * NTOP];
__device__ float g_fos_row[BB * NN];
__device__ float g_vis_row[BB * NN];
__device__ float g_sos_row[BB * NN];

__device__ __forceinline__ uint32_t smem_u32(const void* p) {
    uint32_t a;
    asm("{ .reg .u64 t; cvta.to.shared.u64 t, %1; cvt.u32.u64 %0, t; }"
        : "=r"(a) : "l"(p));
    return a;
}

#define LDMATRIX_X4(r0, r1, r2, r3, addr) \
    asm volatile("ldmatrix.sync.aligned.m8n8.x4.shared.b16 {%0,%1,%2,%3}, [%4];" \
                 : "=r"(r0), "=r"(r1), "=r"(r2), "=r"(r3) : "r"(addr))
#define MMA_BF16(d, a, b) \
    asm volatile("mma.sync.aligned.m16n8k16.row.col.f32.bf16.bf16.f32 " \
                 "{%0,%1,%2,%3}, {%4,%5,%6,%7}, {%8,%9}, {%0,%1,%2,%3};" \
                 : "+f"((d)[0]), "+f"((d)[1]), "+f"((d)[2]), "+f"((d)[3]) \
                 : "r"((a)[0]), "r"((a)[1]), "r"((a)[2]), "r"((a)[3]), \
                   "r"((b)[0]), "r"((b)[1]))

// ---------------------------------------------------------------------------
// Prep (fused): normalize; write fp32 (a, wa, gd) and bf16 hi/lo splits.
// ---------------------------------------------------------------------------
__device__ __forceinline__ void write_split(__nv_bfloat16* dst, int c, float v) {
    __nv_bfloat16 h = __float2bfloat16(v);
    dst[c] = h;
    dst[128 + c] = __float2bfloat16(v - __bfloat162float(h));
}

__global__ void prep_kernel(const float* __restrict__ kp1_desc,
                            const float* __restrict__ w_kp1,
                            const float* __restrict__ desc2) {
    int idx = blockIdx.x;
    const int per_b = 2 * NN + MM;
    int b = idx / per_b;
    int i = idx - b * per_b;
    int c = threadIdx.x;

    float v;
    float* dstf;
    __nv_bfloat16* dsts;
    if (i < NN) {
        v    = kp1_desc[(size_t)(b * NN + i) * CC + c];
        dstf = g_a    + (size_t)(b * NN + i) * CC;
        dsts = g_a_bf + (size_t)(b * NN + i) * 256;
    } else {
        float px, py;
        if (i < 2 * NN) {
            int n = i - NN;
            px   = w_kp1[(size_t)(b * NN + n) * 2 + 0];
            py   = w_kp1[(size_t)(b * NN + n) * 2 + 1];
            dstf = g_wa    + (size_t)(b * NN + n) * CC;
            dsts = g_wa_bf + (size_t)(b * NN + n) * 256;
        } else {
            int m = i - 2 * NN;
            px   = ((float)(m & 31) + 0.5f) * (float)GRIDC;
            py   = ((float)(m >> 5) + 0.5f) * (float)GRIDC;
            dstf = g_gd    + (size_t)(b * MM + m) * CC;
            dsts = g_gd_bf + (size_t)(b * MM + m) * 256;
        }
        float x = fminf(fmaxf(px, 0.0f), (float)(WW - 1));
        float y = fminf(fmaxf(py, 0.0f), (float)(HH - 1));
        float x0f = floorf(x), y0f = floorf(y);
        float wx = x - x0f, wy = y - y0f;
        int x0 = (int)x0f, y0 = (int)y0f;
        int x1 = min(x0 + 1, WW - 1), y1 = min(y0 + 1, HH - 1);
        const float* base = desc2 + (size_t)(b * CC + c) * (HH * WW);
        float v00 = base[y0 * WW + x0];
        float v01 = base[y0 * WW + x1];
        float v10 = base[y1 * WW + x0];
        float v11 = base[y1 * WW + x1];
        v = v00 * (1.0f - wy) * (1.0f - wx) + v01 * (1.0f - wy) * wx
          + v10 * wy * (1.0f - wx)          + v11 * wy * wx;
    }

    __shared__ float red[4];
    float s = v * v;
    #pragma unroll
    for (int o = 16; o > 0; o >>= 1) s += __shfl_down_sync(0xffffffffu, s, o);
    if ((c & 31) == 0) red[c >> 5] = s;
    __syncthreads();
    float tot = red[0] + red[1] + red[2] + red[3];
    v = v / (sqrtf(tot) + 1e-8f);
    dstf[c] = v;
    write_split(dsts, c, v);
}

// ---------------------------------------------------------------------------
__device__ __forceinline__ float compute_vis(const float* __restrict__ kp1,
                                             const float* __restrict__ homo,
                                             int b, int n) {
    float kx = kp1[(size_t)(b * NN + n) * 2 + 0];
    float ky = kp1[(size_t)(b * NN + n) * 2 + 1];
    const float* hm = homo + b * 9;
    float den = hm[6] * kx + hm[7] * ky + hm[8] + 1e-8f;
    float wkx = (hm[0] * kx + hm[1] * ky + hm[2]) / den;
    float wky = (hm[3] * kx + hm[4] * ky + hm[5]) / den;
    return (wkx >= 0.0f && wkx <= (float)(WW - 1) &&
            wky >= 0.0f && wky <= (float)(HH - 1)) ? 1.0f : 0.0f;
}

// ---------------------------------------------------------------------------
// Main kernel (HMMA). Blocks [0,512): FOS; [512,1024): SOS.
// 64x128 tile; approx dot = (hi_a+lo_a)*hi_b = a*hi_b (2 passes, shared B).
// Single load phase, single pre-compute barrier. B fragments hoisted.
// ---------------------------------------------------------------------------
__global__ __launch_bounds__(256, 2) void main_kernel(const float* __restrict__ w_kp1) {
    extern __shared__ char smc[];
    uint32_t sb = smem_u32(smc);
    float* qc = (float*)(smc + SM_QC);
    float* cc = (float*)(smc + SM_CC);

    int tid = threadIdx.x;
    int wid = tid >> 5, lane = tid & 31;
    int wr = wid >> 2, wc = wid & 3;       // 2x4 warp grid, warp tile 32x32
    int bid = blockIdx.x;
    bool is_sos = bid >= HALF_BLOCKS;
    int lbid = is_sos ? bid - HALF_BLOCKS : bid;
    int ct = lbid & (CTILES - 1);
    int qt = (lbid >> 3) & (QT - 1);
    int b  = lbid >> 7;
    int n0 = qt * TQ;
    int m_base = ct * TC;

    const __nv_bfloat16* asrc = (is_sos ? g_wa_bf : g_a_bf) + (size_t)(b * NN + n0) * 256;
    const __nv_bfloat16* bsrc = (is_sos ? g_wa_bf : g_gd_bf)
                              + (size_t)(b * (is_sos ? NN : MM) + m_base) * 256;

    // A full (hi|lo): 64 rows x 32 chunks of 16B = 2048 -> 8/thread
    #pragma unroll
    for (int j = 0; j < 8; j++) {
        int idx = tid + j * 256;
        int r = idx >> 5, c8 = idx & 31;
        *(float4*)(smc + SM_A + r * ROWA + c8 * 16) =
            *(const float4*)(asrc + (size_t)r * 256 + c8 * 8);
    }
    // B hi only: 128 rows x 16 chunks = 2048 -> 8/thread
    #pragma unroll
    for (int j = 0; j < 8; j++) {
        int idx = tid + j * 256;
        int r = idx >> 4, c8 = idx & 15;
        *(float4*)(smc + SM_B + r * ROWB + c8 * 16) =
            *(const float4*)(bsrc + (size_t)r * 256 + c8 * 8);
    }
    // coords
    if (tid < 128) qc[tid] = w_kp1[(size_t)(b * NN + n0 + (tid >> 1)) * 2 + (tid & 1)];
    {
        int r = tid >> 1, comp = tid & 1;
        if (is_sos) {
            cc[tid] = w_kp1[(size_t)(b * NN + m_base + r) * 2 + comp];
        } else {
            int m = m_base + r;
            cc[tid] = comp ? (float)((m >> 5) * GRIDC + 4)
                           : (float)((m & 31) * GRIDC + 4);
        }
    }
    __syncthreads();   // the ONLY pre-compute barrier

    float acc[2][4][4];
    #pragma unroll
    for (int mt = 0; mt < 2; mt++)
        #pragma unroll
        for (int nt = 0; nt < 4; nt++)
            #pragma unroll
            for (int e = 0; e < 4; e++) acc[mt][nt][e] = 0.0f;

    #pragma unroll
    for (int s = 0; s < 8; s++) {
        int k0 = s * 16;
        // B fragments once per k-step (shared across both passes)
        uint32_t bf2[4][2];
        #pragma unroll
        for (int ntp = 0; ntp < 2; ntp++) {
            int g = lane >> 3;
            uint32_t addr = sb + SM_B
                + (uint32_t)(wc * 32 + ntp * 16 + (g >> 1) * 8 + (lane & 7)) * ROWB
                + (uint32_t)(k0 + (g & 1) * 8) * 2;
            uint32_t t0, t1, t2, t3;
            LDMATRIX_X4(t0, t1, t2, t3, addr);   // NON-trans: B stored [n][k]
            bf2[2 * ntp][0] = t0;     bf2[2 * ntp][1] = t1;
            bf2[2 * ntp + 1][0] = t2; bf2[2 * ntp + 1][1] = t3;
        }
        #pragma unroll
        for (int p = 0; p < 2; p++) {
            int aoff = p * 128;
            uint32_t af[2][4];
            #pragma unroll
            for (int mt = 0; mt < 2; mt++) {
                uint32_t addr = sb + SM_A
                    + (uint32_t)(wr * 32 + mt * 16 + (lane & 15)) * ROWA
                    + (uint32_t)(aoff + k0 + (lane >> 4) * 8) * 2;
                LDMATRIX_X4(af[mt][0], af[mt][1], af[mt][2], af[mt][3], addr);
            }
            #pragma unroll
            for (int mt = 0; mt < 2; mt++)
                #pragma unroll
                for (int nt = 0; nt < 4; nt++)
                    MMA_BF16(acc[mt][nt], af[mt], bf2[nt]);
        }
    }
    __syncthreads();   // all ldsm reads done -> smem reusable

    // ---- mask + stage masked dots into dots[64][DSTRIDE] (A region) ----
    float* dots = (float*)smc;
    #pragma unroll
    for (int mt = 0; mt < 2; mt++) {
        #pragma unroll
        for (int rr = 0; rr < 2; rr++) {
            int row = wr * 32 + mt * 16 + (lane >> 2) + rr * 8;
            int n_glob = n0 + row;
            float qx = qc[2 * row], qy = qc[2 * row + 1];
            #pragma unroll
            for (int nt = 0; nt < 4; nt++) {
                int col = wc * 32 + nt * 8 + 2 * (lane & 3);
                float d0 = acc[mt][nt][2 * rr + 0];
                float d1 = acc[mt][nt][2 * rr + 1];
                #pragma unroll
                for (int e = 0; e < 2; e++) {
                    float d = e ? d1 : d0;
                    int cl = col + e;
                    int m = m_base + cl;
                    float dx = qx - cc[2 * cl], dy = qy - cc[2 * cl + 1];
                    bool masked = (dx * dx + dy * dy < 256.0f) ||
                                  (is_sos && m == n_glob);
                    if (e) d1 = masked ? -1e30f : d;
                    else   d0 = masked ? -1e30f : d;
                }
                *(float2*)(dots + (size_t)row * DSTRIDE + col) = make_float2(d0, d1);
            }
        }
    }
    __syncthreads();

    // ---- parallel selection: 4 threads/row, 32 cols each -> top-8 partials --
    float* selv = (float*)(smc + SM_B);            // [64][32]
    int*   seli = (int*)(smc + SM_B + 8192);       // [64][32]
    {
        int row = tid >> 2, q = tid & 3;
        float mv[8]; int mi[8];
        #pragma unroll
        for (int j = 0; j < 8; j++) { mv[j] = -1e30f; mi[j] = 0; }
        float w8 = -1e30f;
        const float* drow = dots + (size_t)row * DSTRIDE + q * 32;
        int mq = m_base + q * 32;
        #pragma unroll 4
        for (int i = 0; i < 32; i++) {
            float val = drow[i];
            if (val > w8) {
                bool done = false;
                #pragma unroll
                for (int j = 0; j < 8; j++)
                    if (!done && mv[j] == w8) { mv[j] = val; mi[j] = mq + i; done = true; }
                w8 = mv[0];
                #pragma unroll
                for (int j = 1; j < 8; j++) w8 = fminf(w8, mv[j]);
            }
        }
        float* pv = selv + row * 32 + q * 8;
        int*   pi = seli + row * 32 + q * 8;
        #pragma unroll
        for (int j = 0; j < 8; j++) { pv[j] = mv[j]; pi[j] = mi[j]; }
    }
    __syncthreads();

    // ---- per-row merge of 32 partials -> top-8 (threads 0..63) ----
    if (tid < TQ) {
        float mv[8]; int mi[8];
        #pragma unroll
        for (int j = 0; j < 8; j++) { mv[j] = -1e30f; mi[j] = 0; }
        float w8 = -1e30f;
        const float* pv = selv + tid * 32;
        const int*   pi = seli + tid * 32;
        #pragma unroll 4
        for (int i = 0; i < 32; i++) {
            float val = pv[i];
            if (val > w8) {
                int ii = pi[i];
                bool done = false;
                #pragma unroll
                for (int j = 0; j < 8; j++)
                    if (!done && mv[j] == w8) { mv[j] = val; mi[j] = ii; done = true; }
                w8 = mv[0];
                #pragma unroll
                for (int j = 1; j < 8; j++) w8 = fminf(w8, mv[j]);
            }
        }
        size_t base = (size_t)(b * NN + n0 + tid) * NTOP + ct * 8;
        if (is_sos) {
            #pragma unroll
            for (int j = 0; j < 8; j++) {
                g_sos_topv[base + j] = mv[j];
                g_sos_topi[base + j] = mi[j];
            }
        } else {
            #pragma unroll
            for (int j = 0; j < 8; j++) {
                g_fos_topv[base + j] = mv[j];
                g_fos_topi[base + j] = mi[j];
            }
        }
    }
}

// ---------------------------------------------------------------------------
__device__ __forceinline__ void bitonic32(float& v, int& i) {
    unsigned lane = threadIdx.x & 31;
    #pragma unroll
    for (int k = 2; k <= 32; k <<= 1) {
        #pragma unroll
        for (int j = k >> 1; j > 0; j >>= 1) {
            float pv = __shfl_xor_sync(0xffffffffu, v, j);
            int   pi = __shfl_xor_sync(0xffffffffu, i, j);
            bool up = ((lane & k) == 0) || (k == 32);
            bool keepmin = (up == ((lane & j) == 0));
            bool take = keepmin ? (pv < v) : (pv > v);
            if (take) { v = pv; i = pi; }
        }
    }
}
// merge 64 partials -> top-16 ascending keys in lanes 0-15
__device__ __forceinline__ void merge_top16(float& key, int& idx, float kB, int iB) {
    unsigned lane = threadIdx.x & 31;
    bitonic32(key, idx);
    bitonic32(kB, iB);
    float kBs = __shfl_sync(0xffffffffu, kB, (lane - 16) & 31);
    int   iBs = __shfl_sync(0xffffffffu, iB, (lane - 16) & 31);
    float cand = (lane < 16) ? key : kBs;
    int   candi = (lane < 16) ? idx : iBs;
    bitonic32(cand, candi);
    key = cand; idx = candi;
}
// exact fp32 rescore of the 16 candidates (2 lanes/candidate), re-rank.
__device__ __forceinline__ void rescore16(float key, int idx,
                                          const float* __restrict__ rowp,
                                          const float* __restrict__ candbase,
                                          float& okey, int& oidx) {
    unsigned lane = threadIdx.x & 31;
    float k_s = __shfl_sync(0xffffffffu, key, lane >> 1);
    int   i_s = __shfl_sync(0xffffffffu, idx, lane >> 1);
    float dp = 0.0f;
    if (k_s < 1e29f) {
        const float4* pr = (const float4*)rowp;
        const float4* pc = (const float4*)(candbase + (size_t)i_s * CC);
        int h = lane & 1;
        #pragma unroll
        for (int kk = 0; kk < 16; kk++) {
            float4 x = pr[h * 16 + kk], y = pc[h * 16 + kk];
            dp += x.x * y.x + x.y * y.y + x.z * y.z + x.w * y.w;
        }
    }
    dp += __shfl_xor_sync(0xffffffffu, dp, 1);
    float ex = __shfl_sync(0xffffffffu, dp, (2 * lane) & 31);
    okey = (lane < 16 && key < 1e29f) ? -ex : 1e30f;
    oidx = idx;
    bitonic32(okey, oidx);
}

// ---------------------------------------------------------------------------
// Epilogue: warp per row; top-16 approx merge -> exact fp32 rescore -> top-8;
// pos, vis, d1 gather.
// ---------------------------------------------------------------------------
__global__ __launch_bounds__(256) void epilogue_kernel(const float* __restrict__ kp1,
                                                       const float* __restrict__ homo) {
    int w = threadIdx.x >> 5, lane = threadIdx.x & 31;
    int row = blockIdx.x * 8 + w;
    int b = row >> 10, n = row & 1023;

    const float* arow  = g_a  + (size_t)row * CC;
    const float* warow = g_wa + (size_t)row * CC;

    float4 av = *(const float4*)(arow  + 4 * lane);
    float4 wv = *(const float4*)(warow + 4 * lane);
    float d0 = av.x - wv.x, d1 = av.y - wv.y, d2 = av.z - wv.z, d3 = av.w - wv.w;
    float s = d0 * d0 + d1 * d1 + d2 * d2 + d3 * d3;
    #pragma unroll
    for (int o = 16; o > 0; o >>= 1) s += __shfl_xor_sync(0xffffffffu, s, o);
    float pos = sqrtf(s);

    // ---- FOS: merge approx top-16, exact rescore vs gd ----
    float fA = -g_fos_topv[(size_t)row * NTOP + lane];
    float fB = -g_fos_topv[(size_t)row * NTOP + 32 + lane];
    int   jA =  g_fos_topi[(size_t)row * NTOP + lane];
    int   jB =  g_fos_topi[(size_t)row * NTOP + 32 + lane];
    merge_top16(fA, jA, fB, jB);
    float fkey; int fidx;
    rescore16(fA, jA, arow, g_gd + (size_t)b * MM * CC, fkey, fidx);
    float fdist = (fkey > 1e29f) ? 10.0f
                                 : sqrtf(fmaxf(2.0f + 2.0f * fkey, 0.0f) + 1e-8f);
    float f = (lane < 8) ? fmaxf(pos - fdist + 1.0f, 0.0f) : 0.0f;
    #pragma unroll
    for (int o = 16; o > 0; o >>= 1) f += __shfl_xor_sync(0xffffffffu, f, o);

    // ---- SOS: merge approx top-16, exact rescore vs wa ----
    float sA = -g_sos_topv[(size_t)row * NTOP + lane];
    float sB = -g_sos_topv[(size_t)row * NTOP + 32 + lane];
    int   iA =  g_sos_topi[(size_t)row * NTOP + lane];
    int   iB =  g_sos_topi[(size_t)row * NTOP + 32 + lane];
    merge_top16(sA, iA, sB, iB);
    float skey; int sidx;
    rescore16(sA, iA, warow, g_wa + (size_t)b * NN * CC, skey, sidx);

    // d1 at the 8 selected indices: quad (4 lanes) per index
    int j = lane >> 2, q = lane & 3;
    float d2neg = __shfl_sync(0xffffffffu, skey, j);
    int   cidx  = __shfl_sync(0xffffffffu, sidx, j);
    const float4* pa = (const float4*)arow;
    const float4* pb = (const float4*)(g_a + (size_t)(b * NN + cidx) * CC);
    float dp = 0.0f;
    #pragma unroll
    for (int kk = 0; kk < 8; kk++) {
        float4 x = pa[q * 8 + kk], y = pb[q * 8 + kk];
        dp += x.x * y.x + x.y * y.y + x.z * y.z + x.w * y.w;
    }
    dp += __shfl_xor_sync(0xffffffffu, dp, 1);
    dp += __shfl_xor_sync(0xffffffffu, dp, 2);
    float d1v = sqrtf(fmaxf(2.0f - 2.0f * dp, 0.0f) + 1e-8f);
    float d2v = sqrtf(fmaxf(2.0f + 2.0f * d2neg, 0.0f) + 1e-8f);
    float t = (d2neg < 1e29f) ? (d1v - d2v) : 0.0f;
    float t2 = (q == 0) ? t * t : 0.0f;
    #pragma unroll
    for (int o = 16; o > 0; o >>= 1) t2 += __shfl_xor_sync(0xffffffffu, t2, o);

    if (lane == 0) {
        float vis = compute_vis(kp1, homo, b, n);
        g_fos_row[row] = f * vis;
        g_vis_row[row] = vis;
        g_sos_row[row] = sqrtf(t2 + 1e-8f) * vis;
    }
}

// ---------------------------------------------------------------------------
__global__ void finalize_kernel(float* __restrict__ out) {
    __shared__ float sf[1024], sv[1024], ss[1024];
    int t = threadIdx.x;
    float f = 0.0f, v = 0.0f, s = 0.0f;
    #pragma unroll
    for (int i = 0; i < 4; i++) {
        f += g_fos_row[t + 1024 * i];
        v += g_vis_row[t + 1024 * i];
        s += g_sos_row[t + 1024 * i];
    }
    sf[t] = f; sv[t] = v; ss[t] = s;
    __syncthreads();
    for (int o = 512; o > 0; o >>= 1) {
        if (t < o) {
            sf[t] += sf[t + o];
            sv[t] += sv[t + o];
            ss[t] += ss[t + o];
        }
        __syncthreads();
    }
    if (t == 0) {
        float cnt = fmaxf(sv[0], 1.0f);
        out[0] = sf[0] / (cnt * 8.0f) + ss[0] / cnt;
    }
}

// ---------------------------------------------------------------------------
extern "C" void kernel_launch(void* const* d_in, const int* in_sizes, int n_in,
                              void* d_out, int out_size) {
    const float* kp1      = (const float*)d_in[0];
    const float* w_kp1    = (const float*)d_in[1];
    const float* kp1_desc = (const float*)d_in[2];
    const float* desc2    = (const float*)d_in[3];
    const float* homo12   = (const float*)d_in[4];
    (void)in_sizes; (void)n_in; (void)out_size;

    cudaFuncSetAttribute(main_kernel,
                         cudaFuncAttributeMaxDynamicSharedMemorySize, SMEM_TOTAL);

    prep_kernel<<<BB * (2 * NN + MM), CC>>>(kp1_desc, w_kp1, desc2);
    main_kernel<<<MAIN_BLOCKS, 256, SMEM_TOTAL>>>(w_kp1);
    epilogue_kernel<<<BB * NN / 8, 256>>>(kp1, homo12);
    finalize_kernel<<<1, 1024>>>((float*)d_out);
}